// round 13
// baseline (speedup 1.0000x reference)
#include <cuda_runtime.h>
#include <cuda_bf16.h>

// Problem constants
#define BATCH 32
#define CH    256
#define HH    64
#define WW    64
#define HW    (HH*WW)            // 4096
#define HW4   (HW/4)             // 1024 float4 per image plane
#define EPSV  1e-5f

#define GROUP    32              // CTAs per image
#define PIX      32              // float4 pixels per pool CTA
#define CHUNKS   8               // channel chunks per pool CTA
#define CPC      (CH/CHUNKS)     // 32 channels per chunk

// Scratch (allocation-free rule: __device__ globals)
__device__ float g_pooled[BATCH * 2 * HW];   // [B, {max,mean}, H, W]
__device__ float g_att[BATCH * HW];          // [B, H, W]
__device__ int   g_cnt_pool[BATCH];
__device__ int   g_cnt_att[BATCH];

__global__ void init_kernel() {
    int t = threadIdx.x;
    if (t < BATCH) { g_cnt_pool[t] = 0; g_cnt_att[t] = 0; }
}

__device__ __forceinline__ void spin_until(volatile int* p, int target) {
    while (*p < target) { __nanosleep(32); }
}

// ---------------------------------------------------------------------------
// All-phase CTA: pool chunk -> (r<4: att quarter) -> mul 8 planes, all for
// the SAME image b = bid/32. Every resident CTA streams x during the pool
// phase (no idle roles); the pool->mul gap is just the att latency, so the
// x re-read in phase 3 hits L2.
// ---------------------------------------------------------------------------
__global__ __launch_bounds__(256, 6) void pipeline_kernel(
        const float* __restrict__ x, float* __restrict__ out,
        const float* __restrict__ w1,
        const float* __restrict__ g1, const float* __restrict__ b1,
        const float* __restrict__ m1, const float* __restrict__ v1,
        const float* __restrict__ w2,
        const float* __restrict__ g2, const float* __restrict__ b2,
        const float* __restrict__ m2, const float* __restrict__ v2,
        const float* __restrict__ w3,
        const float* __restrict__ g3, const float* __restrict__ b3,
        const float* __restrict__ m3, const float* __restrict__ v3) {
    __shared__ float4 smx[CHUNKS * PIX];
    __shared__ float4 ssm[CHUNKS * PIX];

    const int tid = threadIdx.x;
    const int b   = blockIdx.x >> 5;          // image
    const int r   = blockIdx.x & (GROUP - 1); // role within group

    // ================= Phase 1: POOL chunk r of image b =================
    {
        int pix   = tid & (PIX - 1);
        int chunk = tid >> 5;
        int p4base = r * PIX;
        int p4     = p4base + pix;

        const float4* xb = (const float4*)(x + (size_t)b * CH * HW) + p4
                         + (size_t)(chunk * CPC) * HW4;
        float4 v  = xb[0];
        float4 mx = v, sm = v;
#pragma unroll
        for (int c = 1; c < CPC; c++) {
            float4 t = xb[(size_t)c * HW4];
            mx.x = fmaxf(mx.x, t.x); mx.y = fmaxf(mx.y, t.y);
            mx.z = fmaxf(mx.z, t.z); mx.w = fmaxf(mx.w, t.w);
            sm.x += t.x; sm.y += t.y; sm.z += t.z; sm.w += t.w;
        }
        smx[tid] = mx;
        ssm[tid] = sm;
        __syncthreads();

#pragma unroll
        for (int s = 128; s >= PIX; s >>= 1) {
            if (tid < s) {
                float4 am = smx[tid], bm = smx[tid + s];
                am.x = fmaxf(am.x, bm.x); am.y = fmaxf(am.y, bm.y);
                am.z = fmaxf(am.z, bm.z); am.w = fmaxf(am.w, bm.w);
                smx[tid] = am;
                float4 as = ssm[tid], bs = ssm[tid + s];
                as.x += bs.x; as.y += bs.y; as.z += bs.z; as.w += bs.w;
                ssm[tid] = as;
            }
            __syncthreads();
        }

        if (tid < PIX) {
            const float inv = 1.0f / (float)CH;
            float4 mxr = smx[tid];
            float4 smr = ssm[tid];
            float4 av = make_float4(smr.x*inv, smr.y*inv, smr.z*inv, smr.w*inv);
            float4* pmax = (float4*)(g_pooled + (size_t)b * 2 * HW) + p4base + tid;
            float4* pavg = (float4*)(g_pooled + (size_t)b * 2 * HW + HW) + p4base + tid;
            *pmax = mxr;
            *pavg = av;
        }
        __syncthreads();
        __threadfence();
        if (tid == 0) atomicAdd(&g_cnt_pool[b], 1);
    }

    // ================= Phase 2 (r<4): ATT quarter of image b =================
    if (r < 4) {
        float* ws   = (float*)smx;     // reuse smem: 294 floats + 3
        float* bias = ws + 3 * 2 * 49;
        __syncthreads();               // phase-1 smem reads done

        if (tid < 3) {
            const float* gg = (tid == 0) ? g1 : (tid == 1) ? g2 : g3;
            const float* be = (tid == 0) ? b1 : (tid == 1) ? b2 : b3;
            const float* mm = (tid == 0) ? m1 : (tid == 1) ? m2 : m3;
            const float* vv = (tid == 0) ? v1 : (tid == 1) ? v2 : v3;
            float s = gg[0] * rsqrtf(vv[0] + EPSV);
            bias[tid] = be[0] - mm[0] * s;
        }
        for (int k = tid; k < 3 * 2 * 49; k += 256) {
            int br = k / 98, rr = k % 98, i = rr / 49, kk = rr % 49;
            int kh = kk / 7, kw = kk % 7;
            float s, raw;
            if (br == 0)      { s = g1[0]*rsqrtf(v1[0]+EPSV); raw = w1[i*49 + kh*7 + kw]; }
            else if (br == 1) { s = g2[0]*rsqrtf(v2[0]+EPSV); raw = w2[i*49 + kw*7 + kh]; }
            else              { s = g3[0]*rsqrtf(v3[0]+EPSV); raw = w3[i*49 + kh*7 + kw]; }
            ws[k] = raw * s;
        }

        if (tid == 0) spin_until(&g_cnt_pool[b], GROUP);
        __syncthreads();
        __threadfence();

        const float* pmax = g_pooled + (size_t)b * 2 * HW;
        const float* pavg = pmax + HW;

#pragma unroll
        for (int i = 0; i < 4; i++) {
            int px = r * 1024 + i * 256 + tid;
            int h = px >> 6, w = px & 63;
            float acc0 = 0.f, acc1 = 0.f, acc2 = 0.f;
#pragma unroll
            for (int kh = 0; kh < 7; kh++) {
                int hh = h + kh - 3;
                if (hh < 0 || hh >= HH) continue;
#pragma unroll
                for (int kw = 0; kw < 7; kw++) {
                    int wv = w + kw - 3;
                    if (wv < 0 || wv >= WW) continue;
                    int off = hh * WW + wv;
                    float pm = pmax[off];
                    float pa = pavg[off];
                    int kk = kh * 7 + kw;
                    acc0 = fmaf(ws[0*98 + 0*49 + kk], pm, acc0);
                    acc0 = fmaf(ws[0*98 + 1*49 + kk], pa, acc0);
                    acc1 = fmaf(ws[1*98 + 0*49 + kk], pm, acc1);
                    acc1 = fmaf(ws[1*98 + 1*49 + kk], pa, acc1);
                    acc2 = fmaf(ws[2*98 + 0*49 + kk], pm, acc2);
                    acc2 = fmaf(ws[2*98 + 1*49 + kk], pa, acc2);
                }
            }
            float e0 = 1.0f / (1.0f + __expf(-(acc0 + bias[0])));
            float e1 = 1.0f / (1.0f + __expf(-(acc1 + bias[1])));
            float e2 = 1.0f / (1.0f + __expf(-(acc2 + bias[2])));
            g_att[(size_t)b * HW + px] = (e0 + e1 + e2) * (1.0f / 3.0f);
        }
        __syncthreads();
        __threadfence();
        if (tid == 0) atomicAdd(&g_cnt_att[b], 1);
    }

    // ================= Phase 3: MUL 8 planes of image b =================
    {
        if (tid == 0) spin_until(&g_cnt_att[b], 4);
        __syncthreads();
        __threadfence();

        const float4* ap = (const float4*)g_att + (size_t)b * HW4;
        float4 av[4];
#pragma unroll
        for (int i = 0; i < 4; i++) av[i] = ap[tid + i * 256];

        size_t plane0 = (size_t)b * CH + (size_t)r * 8;
        const float4* xp = (const float4*)x + plane0 * HW4;
        float4*       op = (float4*)out     + plane0 * HW4;

#pragma unroll 2
        for (int ch = 0; ch < 8; ch++) {
            float4 xv[4];
#pragma unroll
            for (int i = 0; i < 4; i++) xv[i] = xp[(size_t)ch * HW4 + tid + i * 256];
#pragma unroll
            for (int i = 0; i < 4; i++) {
                float4 o;
                o.x = xv[i].x * av[i].x; o.y = xv[i].y * av[i].y;
                o.z = xv[i].z * av[i].z; o.w = xv[i].w * av[i].w;
                __stcs(op + (size_t)ch * HW4 + tid + i * 256, o);
            }
        }
    }
}

extern "C" void kernel_launch(void* const* d_in, const int* in_sizes, int n_in,
                              void* d_out, int out_size) {
    const float* x  = (const float*)d_in[0];
    const float* w1 = (const float*)d_in[1];
    const float* g1 = (const float*)d_in[2];
    const float* b1 = (const float*)d_in[3];
    const float* m1 = (const float*)d_in[4];
    const float* v1 = (const float*)d_in[5];
    const float* w2 = (const float*)d_in[6];
    const float* g2 = (const float*)d_in[7];
    const float* b2 = (const float*)d_in[8];
    const float* m2 = (const float*)d_in[9];
    const float* v2 = (const float*)d_in[10];
    const float* w3 = (const float*)d_in[11];
    const float* g3 = (const float*)d_in[12];
    const float* b3 = (const float*)d_in[13];
    const float* m3 = (const float*)d_in[14];
    const float* v3 = (const float*)d_in[15];
    float* out = (float*)d_out;

    init_kernel<<<1, 64>>>();
    pipeline_kernel<<<BATCH * GROUP, 256>>>(
        x, out,
        w1, g1, b1, m1, v1,
        w2, g2, b2, m2, v2,
        w3, g3, b3, m3, v3);
}

// round 14
// speedup vs baseline: 1.3027x; 1.3027x over previous
#include <cuda_runtime.h>
#include <cuda_bf16.h>

// Problem constants
#define BATCH 32
#define CH    256
#define HH    64
#define WW    64
#define HW    (HH*WW)            // 4096
#define HW4   (HW/4)             // 1024 float4 per image plane
#define EPSV  1e-5f

#define CHUNKS   8               // channel chunks per block (pool)
#define CPC      (CH/CHUNKS)     // 32 channels per chunk
#define PIX      32              // float4 pixels per block (pool)

#define MPLANES  4               // planes per mul CTA

// Scratch (allocation-free rule: __device__ globals)
__device__ float g_pooled[BATCH * 2 * HW];   // [B, {max,mean}, H, W]
__device__ float g_att[BATCH * HW];          // [B, H, W]

// ---------------------------------------------------------------------------
// Kernel 1: channel pooling (max + mean over C) -> g_pooled  (R1-proven)
// Block = 256 threads = 32 float4-pixels x 8 channel-chunks, grid = 1024.
// ---------------------------------------------------------------------------
__global__ __launch_bounds__(256) void pool_kernel(const float* __restrict__ x) {
    __shared__ float4 smx[CHUNKS * PIX];
    __shared__ float4 ssm[CHUNKS * PIX];

    int tid   = threadIdx.x;
    int pix   = tid & (PIX - 1);       // 0..31
    int chunk = tid >> 5;              // 0..7

    int blk    = blockIdx.x;           // 0..1023
    int b      = blk >> 5;             // 32 blocks per batch
    int p4base = (blk & 31) * PIX;
    int p4     = p4base + pix;

    const float4* xb = (const float4*)(x + (size_t)b * CH * HW) + p4
                     + (size_t)(chunk * CPC) * HW4;

    float4 v  = xb[0];
    float4 mx = v;
    float4 sm = v;
#pragma unroll
    for (int c = 1; c < CPC; c++) {
        float4 t = xb[(size_t)c * HW4];
        mx.x = fmaxf(mx.x, t.x); mx.y = fmaxf(mx.y, t.y);
        mx.z = fmaxf(mx.z, t.z); mx.w = fmaxf(mx.w, t.w);
        sm.x += t.x; sm.y += t.y; sm.z += t.z; sm.w += t.w;
    }
    smx[tid] = mx;
    ssm[tid] = sm;
    __syncthreads();

#pragma unroll
    for (int s = 128; s >= PIX; s >>= 1) {
        if (tid < s) {
            float4 am = smx[tid], bm = smx[tid + s];
            am.x = fmaxf(am.x, bm.x); am.y = fmaxf(am.y, bm.y);
            am.z = fmaxf(am.z, bm.z); am.w = fmaxf(am.w, bm.w);
            smx[tid] = am;
            float4 as = ssm[tid], bs = ssm[tid + s];
            as.x += bs.x; as.y += bs.y; as.z += bs.z; as.w += bs.w;
            ssm[tid] = as;
        }
        __syncthreads();
    }

    if (tid < PIX) {
        const float inv = 1.0f / (float)CH;
        float4 mxr = smx[tid];
        float4 smr = ssm[tid];
        float4 av = make_float4(smr.x * inv, smr.y * inv, smr.z * inv, smr.w * inv);
        float4* pmax = (float4*)(g_pooled + (size_t)b * 2 * HW) + p4base + tid;
        float4* pavg = (float4*)(g_pooled + (size_t)b * 2 * HW + HW) + p4base + tid;
        *pmax = mxr;
        *pavg = av;
    }
}

// ---------------------------------------------------------------------------
// Kernel 2: 3x (7x7 conv 2->1 + BN + sigmoid), averaged -> g_att  (R1-proven)
// ---------------------------------------------------------------------------
__global__ void att_kernel(const float* __restrict__ w1,
                           const float* __restrict__ g1, const float* __restrict__ b1,
                           const float* __restrict__ m1, const float* __restrict__ v1,
                           const float* __restrict__ w2,
                           const float* __restrict__ g2, const float* __restrict__ b2,
                           const float* __restrict__ m2, const float* __restrict__ v2,
                           const float* __restrict__ w3,
                           const float* __restrict__ g3, const float* __restrict__ b3,
                           const float* __restrict__ m3, const float* __restrict__ v3) {
    __shared__ float ws[3][2][49];   // BN-scaled effective weights
    __shared__ float bias[3];

    int tid = threadIdx.x;

    if (tid < 3) {
        const float* g  = (tid == 0) ? g1 : (tid == 1) ? g2 : g3;
        const float* be = (tid == 0) ? b1 : (tid == 1) ? b2 : b3;
        const float* m  = (tid == 0) ? m1 : (tid == 1) ? m2 : m3;
        const float* v  = (tid == 0) ? v1 : (tid == 1) ? v2 : v3;
        float s = g[0] * rsqrtf(v[0] + EPSV);
        bias[tid] = be[0] - m[0] * s;
    }

    for (int k = tid; k < 3 * 2 * 49; k += blockDim.x) {
        int br = k / 98;
        int r  = k % 98;
        int i  = r / 49;
        int kk = r % 49;
        int kh = kk / 7, kw = kk % 7;
        float s, raw;
        if (br == 0) {
            s = g1[0] * rsqrtf(v1[0] + EPSV);
            raw = w1[i * 49 + kh * 7 + kw];
        } else if (br == 1) {
            s = g2[0] * rsqrtf(v2[0] + EPSV);
            raw = w2[i * 49 + kw * 7 + kh];   // transposed kernel
        } else {
            s = g3[0] * rsqrtf(v3[0] + EPSV);
            raw = w3[i * 49 + kh * 7 + kw];
        }
        ws[br][i][kk] = raw * s;
    }
    __syncthreads();

    int blk = blockIdx.x;
    int b = blk >> 4;                 // / 16
    int row_base = (blk & 15) * 4;
    int h = row_base + (tid >> 6);
    int w = tid & 63;

    const float* pmax = g_pooled + (size_t)b * 2 * HW;
    const float* pavg = pmax + HW;

    float acc0 = 0.f, acc1 = 0.f, acc2 = 0.f;
#pragma unroll
    for (int kh = 0; kh < 7; kh++) {
        int hh = h + kh - 3;
        if (hh < 0 || hh >= HH) continue;
#pragma unroll
        for (int kw = 0; kw < 7; kw++) {
            int wv = w + kw - 3;
            if (wv < 0 || wv >= WW) continue;
            int off = hh * WW + wv;
            float pm = pmax[off];
            float pa = pavg[off];
            int kk = kh * 7 + kw;
            acc0 = fmaf(ws[0][0][kk], pm, acc0);
            acc0 = fmaf(ws[0][1][kk], pa, acc0);
            acc1 = fmaf(ws[1][0][kk], pm, acc1);
            acc1 = fmaf(ws[1][1][kk], pa, acc1);
            acc2 = fmaf(ws[2][0][kk], pm, acc2);
            acc2 = fmaf(ws[2][1][kk], pa, acc2);
        }
    }
    float s0 = 1.0f / (1.0f + __expf(-(acc0 + bias[0])));
    float s1 = 1.0f / (1.0f + __expf(-(acc1 + bias[1])));
    float s2 = 1.0f / (1.0f + __expf(-(acc2 + bias[2])));
    g_att[(size_t)b * HW + h * WW + w] = (s0 + s1 + s2) * (1.0f / 3.0f);
}

// ---------------------------------------------------------------------------
// Kernel 3: out = x * att.
// 4 planes per CTA (grid 2048): att slice loaded ONCE per CTA (4 f4) and
// reused across all 4 planes (cuts redundant att L2 reads 4x). x loads
// front-batched 8 LDG.128 deep (2 planes per batch). __stcs stores.
// ---------------------------------------------------------------------------
__global__ __launch_bounds__(256) void mul_kernel(const float* __restrict__ x,
                                                  float* __restrict__ out) {
    int blk = blockIdx.x;              // [0, BATCH*CH/MPLANES)
    int tid = threadIdx.x;
    int b   = blk >> 6;                // 64 blocks per image (256/4 planes)

    size_t plane0 = (size_t)blk * MPLANES;
    const float4* xp = (const float4*)x + plane0 * HW4;
    float4*       op = (float4*)out    + plane0 * HW4;
    const float4* ap = (const float4*)g_att + (size_t)b * HW4;

    // att slice for this thread, reused for all planes
    float4 av[4];
#pragma unroll
    for (int i = 0; i < 4; i++) av[i] = ap[tid + i * 256];

#pragma unroll
    for (int pp = 0; pp < MPLANES; pp += 2) {
        float4 xv[8];
#pragma unroll
        for (int i = 0; i < 4; i++)
            xv[i]     = xp[(size_t)pp * HW4 + tid + i * 256];
#pragma unroll
        for (int i = 0; i < 4; i++)
            xv[4 + i] = xp[(size_t)(pp + 1) * HW4 + tid + i * 256];
#pragma unroll
        for (int i = 0; i < 4; i++) {
            float4 o;
            o.x = xv[i].x * av[i].x; o.y = xv[i].y * av[i].y;
            o.z = xv[i].z * av[i].z; o.w = xv[i].w * av[i].w;
            __stcs(op + (size_t)pp * HW4 + tid + i * 256, o);
        }
#pragma unroll
        for (int i = 0; i < 4; i++) {
            float4 o;
            o.x = xv[4+i].x * av[i].x; o.y = xv[4+i].y * av[i].y;
            o.z = xv[4+i].z * av[i].z; o.w = xv[4+i].w * av[i].w;
            __stcs(op + (size_t)(pp + 1) * HW4 + tid + i * 256, o);
        }
    }
}

extern "C" void kernel_launch(void* const* d_in, const int* in_sizes, int n_in,
                              void* d_out, int out_size) {
    const float* x  = (const float*)d_in[0];
    const float* w1 = (const float*)d_in[1];
    const float* g1 = (const float*)d_in[2];
    const float* b1 = (const float*)d_in[3];
    const float* m1 = (const float*)d_in[4];
    const float* v1 = (const float*)d_in[5];
    const float* w2 = (const float*)d_in[6];
    const float* g2 = (const float*)d_in[7];
    const float* b2 = (const float*)d_in[8];
    const float* m2 = (const float*)d_in[9];
    const float* v2 = (const float*)d_in[10];
    const float* w3 = (const float*)d_in[11];
    const float* g3 = (const float*)d_in[12];
    const float* b3 = (const float*)d_in[13];
    const float* m3 = (const float*)d_in[14];
    const float* v3 = (const float*)d_in[15];
    float* out = (float*)d_out;

    // K1: pooling  (1024 blocks, R1-proven)
    pool_kernel<<<BATCH * HW4 / PIX, 256>>>(x);

    // K2: attention map
    att_kernel<<<BATCH * (HH / 4), 256>>>(w1, g1, b1, m1, v1,
                                          w2, g2, b2, m2, v2,
                                          w3, g3, b3, m3, v3);

    // K3: elementwise multiply, 4 planes per CTA (2048 blocks)
    mul_kernel<<<BATCH * CH / MPLANES, 256>>>(x, out);
}